// round 12
// baseline (speedup 1.0000x reference)
#include <cuda_runtime.h>
#include <math.h>

#define NB 64
#define NT 4096
#define NU 256
#define NDEC 256
#define NSPLIT 16
#define CHUNK (NT / NSPLIT)           // 256 tokens per CTA
#define NWARPS 8
#define TOK_PER_WARP (CHUNK / NWARPS) // 32

// ---- scratch (no allocations allowed; __device__ globals are zero-init) ----
__device__ float g_state[NB * NU];            // Wa(decoder_s)
__device__ float g_score[NB * NT];            // raw scores (valid tokens only)
__device__ float g_part_m[NB * NSPLIT];
__device__ float g_part_d[NB * NSPLIT];
__device__ float g_part_ct[NB * NSPLIT * NU];
__device__ int   g_cnt[NB * NSPLIT];          // valid tokens per chunk

// ---------------------------------------------------------------------------
// Pass 0: state[b,u] = sum_k decoder_s[b,k] * Wa_w[k,u] + Wa_b[u]
// grid = NB*8 CTAs: one per (batch, 32-u column group).
// block 256 = 8 K-groups x 32 u. Each WARP owns a 32-row K-slice of one
// 32-column W panel: every load is 128B-contiguous across the warp, and each
// thread issues 32 fully-independent loads (front-batched -> ~2 DRAM waves).
// ---------------------------------------------------------------------------
#define KG 8
#define UG 32
__global__ __launch_bounds__(256)
void k_state(const float* __restrict__ dec,
             const float* __restrict__ W,
             const float* __restrict__ bias) {
    const int b   = blockIdx.x >> 3;          // batch
    const int ug  = blockIdx.x & 7;           // which 32-u column group
    const int tid = threadIdx.x;
    const int kg  = tid >> 5;                 // K-group 0..7 (== warp id)
    const int ul  = tid & 31;                 // u within group (== lane)
    const int u   = ug * UG + ul;

    __shared__ float sdec[NDEC];
    sdec[tid] = dec[b * NDEC + tid];
    __syncthreads();

    const float* __restrict__ Wp = W + (size_t)(kg * (NDEC / KG)) * NU + u;
    const float* __restrict__ dp = sdec + kg * (NDEC / KG);
    float acc = 0.f;
#pragma unroll
    for (int k = 0; k < NDEC / KG; ++k)       // 32 independent loads, unrolled
        acc = fmaf(dp[k], Wp[(size_t)k * NU], acc);

    __shared__ float sacc[KG][UG];
    sacc[kg][ul] = acc;
    __syncthreads();
    if (kg == 0) {
        float r = 0.f;
#pragma unroll
        for (int i = 0; i < KG; ++i) r += sacc[i][ul];
        g_state[b * NU + u] = r + bias[u];
    }
}

// ---------------------------------------------------------------------------
// Pass 1: fused score + online softmax + context partials.
// One CTA per (batch, T-chunk). Valid count computed once by ballot (mask is
// left-packed), then a clean counted loop: 4-token unroll, 8 LDG.128/thread
// in flight, 4 interleaved butterfly reductions, deferred softmax update.
// ---------------------------------------------------------------------------
__global__ __launch_bounds__(256, 3)
void k_scores(const float* __restrict__ h, const int* __restrict__ mask) {
    const int b    = blockIdx.x / NSPLIT;
    const int c    = blockIdx.x % NSPLIT;
    const int tid  = threadIdx.x;
    const int w    = tid >> 5;
    const int lane = tid & 31;
    const int bT   = b * NT;
    const int chunk0 = c * CHUNK;

    // --- chunk valid count: one mask element per thread, popc(ballot) ---
    __shared__ int swcnt[NWARPS];
    {
        int mv = mask[bT + chunk0 + tid];
        unsigned bal = __ballot_sync(0xFFFFFFFFu, mv != 0);
        if (lane == 0) swcnt[w] = __popc(bal);
    }
    __syncthreads();
    int cnt = 0;
#pragma unroll
    for (int i = 0; i < NWARPS; ++i) cnt += swcnt[i];
    if (tid == 0) g_cnt[b * NSPLIT + c] = cnt;

    // tokens this warp owns (contiguous block, clipped by valid count)
    const int start = w * TOK_PER_WARP;
    int my_n = cnt - start;
    my_n = my_n < 0 ? 0 : (my_n > TOK_PER_WARP ? TOK_PER_WARP : my_n);
    const int tbase = bT + chunk0 + start;

    const float4* st4 = (const float4*)(g_state + b * NU);
    const float4 s0 = st4[lane];
    const float4 s1 = st4[32 + lane];

    float  m = -INFINITY, d = 0.f;
    float4 ct0 = make_float4(0.f, 0.f, 0.f, 0.f);
    float4 ct1 = make_float4(0.f, 0.f, 0.f, 0.f);

    int k = 0;
    for (; k + 4 <= my_n; k += 4) {
        // 8 independent LDG.128 per thread
        float4 a0, a1, b0, b1, c0v, c1v, d0, d1;
        {
            const float4* p0 = (const float4*)(h + (size_t)(tbase + k + 0) * NU);
            const float4* p1 = (const float4*)(h + (size_t)(tbase + k + 1) * NU);
            const float4* p2 = (const float4*)(h + (size_t)(tbase + k + 2) * NU);
            const float4* p3 = (const float4*)(h + (size_t)(tbase + k + 3) * NU);
            a0 = p0[lane]; a1 = p0[32 + lane];
            b0 = p1[lane]; b1 = p1[32 + lane];
            c0v = p2[lane]; c1v = p2[32 + lane];
            d0 = p3[lane]; d1 = p3[32 + lane];
        }
        // 4 independent dot partials
        float p0 = s0.x*a0.x + s0.y*a0.y + s0.z*a0.z + s0.w*a0.w
                 + s1.x*a1.x + s1.y*a1.y + s1.z*a1.z + s1.w*a1.w;
        float p1 = s0.x*b0.x + s0.y*b0.y + s0.z*b0.z + s0.w*b0.w
                 + s1.x*b1.x + s1.y*b1.y + s1.z*b1.z + s1.w*b1.w;
        float p2 = s0.x*c0v.x + s0.y*c0v.y + s0.z*c0v.z + s0.w*c0v.w
                 + s1.x*c1v.x + s1.y*c1v.y + s1.z*c1v.z + s1.w*c1v.w;
        float p3 = s0.x*d0.x + s0.y*d0.y + s0.z*d0.z + s0.w*d0.w
                 + s1.x*d1.x + s1.y*d1.y + s1.z*d1.z + s1.w*d1.w;
        // interleaved butterfly reductions (4 chains overlap)
#pragma unroll
        for (int o = 16; o; o >>= 1) {
            p0 += __shfl_xor_sync(0xFFFFFFFFu, p0, o);
            p1 += __shfl_xor_sync(0xFFFFFFFFu, p1, o);
            p2 += __shfl_xor_sync(0xFFFFFFFFu, p2, o);
            p3 += __shfl_xor_sync(0xFFFFFFFFu, p3, o);
        }
        // lanes 0..3 write the 4 scores (all lanes hold all values)
        {
            float psel = p0;
            if (lane == 1) psel = p1;
            else if (lane == 2) psel = p2;
            else if (lane == 3) psel = p3;
            if (lane < 4) g_score[tbase + k + lane] = psel;
        }
        // deferred online-softmax update (one corr per 4 tokens)
        float nm = fmaxf(fmaxf(fmaxf(p0, p1), fmaxf(p2, p3)), m);
        const float corr = __expf(m - nm);      // exp(-inf)=0 on first block
        const float e0 = __expf(p0 - nm);
        const float e1 = __expf(p1 - nm);
        const float e2 = __expf(p2 - nm);
        const float e3 = __expf(p3 - nm);
        d = d * corr + (e0 + e1) + (e2 + e3);
        ct0.x = ct0.x*corr + e0*a0.x + e1*b0.x + e2*c0v.x + e3*d0.x;
        ct0.y = ct0.y*corr + e0*a0.y + e1*b0.y + e2*c0v.y + e3*d0.y;
        ct0.z = ct0.z*corr + e0*a0.z + e1*b0.z + e2*c0v.z + e3*d0.z;
        ct0.w = ct0.w*corr + e0*a0.w + e1*b0.w + e2*c0v.w + e3*d0.w;
        ct1.x = ct1.x*corr + e0*a1.x + e1*b1.x + e2*c1v.x + e3*d1.x;
        ct1.y = ct1.y*corr + e0*a1.y + e1*b1.y + e2*c1v.y + e3*d1.y;
        ct1.z = ct1.z*corr + e0*a1.z + e1*b1.z + e2*c1v.z + e3*d1.z;
        ct1.w = ct1.w*corr + e0*a1.w + e1*b1.w + e2*c1v.w + e3*d1.w;
        m = nm;
    }
    // remainder (<= 3 tokens)
    for (; k < my_n; ++k) {
        const float4* hp = (const float4*)(h + (size_t)(tbase + k) * NU);
        const float4 h0 = hp[lane];
        const float4 h1 = hp[32 + lane];
        float p = s0.x*h0.x + s0.y*h0.y + s0.z*h0.z + s0.w*h0.w
                + s1.x*h1.x + s1.y*h1.y + s1.z*h1.z + s1.w*h1.w;
#pragma unroll
        for (int o = 16; o; o >>= 1) p += __shfl_xor_sync(0xFFFFFFFFu, p, o);
        if (lane == 0) g_score[tbase + k] = p;
        const float nm = fmaxf(m, p);
        const float corr = __expf(m - nm);
        const float pe = __expf(p - nm);
        d = d * corr + pe;
        ct0.x = ct0.x*corr + pe*h0.x;  ct0.y = ct0.y*corr + pe*h0.y;
        ct0.z = ct0.z*corr + pe*h0.z;  ct0.w = ct0.w*corr + pe*h0.w;
        ct1.x = ct1.x*corr + pe*h1.x;  ct1.y = ct1.y*corr + pe*h1.y;
        ct1.z = ct1.z*corr + pe*h1.z;  ct1.w = ct1.w*corr + pe*h1.w;
        m = nm;
    }

    // --- CTA-level merge of the 8 warps' partials ---
    __shared__ float sct[NWARPS][NU];   // 8 KB
    __shared__ float sm[NWARPS], sd[NWARPS];
    ((float4*)sct[w])[lane]      = ct0;
    ((float4*)sct[w])[32 + lane] = ct1;
    if (lane == 0) { sm[w] = m; sd[w] = d; }
    __syncthreads();

    const int u = tid;
    float M = -INFINITY;
#pragma unroll
    for (int i = 0; i < NWARPS; ++i) M = fmaxf(M, sm[i]);
    float D = 0.f, ctv = 0.f;
#pragma unroll
    for (int i = 0; i < NWARPS; ++i) {
        const float mi = sm[i];
        const float sc = (mi == -INFINITY) ? 0.f : __expf(mi - M);
        D   += sc * sd[i];
        ctv += sc * sct[i][u];
    }
    const int part = b * NSPLIT + c;
    if (tid == 0) { g_part_m[part] = M; g_part_d[part] = D; }
    g_part_ct[part * NU + u] = ctv;
}

// ---------------------------------------------------------------------------
// Pass 2 (fused): merge NSPLIT partials -> ct_sum, then alpha for the whole
// batch row. One CTA per batch, 1024 threads, smem handoff of (M, invD, len).
// ---------------------------------------------------------------------------
__global__ __launch_bounds__(1024)
void k_final(float* __restrict__ out_ct, float* __restrict__ out_a) {
    const int b = blockIdx.x, tid = threadIdx.x;
    __shared__ float sM, sInvD;
    __shared__ int   sLen;

    if (tid < NU) {
        const int u = tid;
        float M = -INFINITY;
#pragma unroll
        for (int i = 0; i < NSPLIT; ++i) M = fmaxf(M, g_part_m[b * NSPLIT + i]);
        float D = 0.f, ct = 0.f;
#pragma unroll
        for (int i = 0; i < NSPLIT; ++i) {
            const float mi = g_part_m[b * NSPLIT + i];
            const float sc = (mi == -INFINITY) ? 0.f : __expf(mi - M);
            D  += sc * g_part_d[b * NSPLIT + i];
            ct += sc * g_part_ct[(b * NSPLIT + i) * NU + u];
        }
        const float invD = 1.f / D;   // D > 0: lengths >= T/4
        out_ct[b * NU + u] = ct * invD;
        if (tid == 0) {
            int L = 0;
#pragma unroll
            for (int i = 0; i < NSPLIT; ++i) L += g_cnt[b * NSPLIT + i];
            sM = M; sInvD = invD; sLen = L;
        }
    }
    __syncthreads();

    const float M = sM, invD = sInvD;
    const int len = sLen;
    // 4096 tokens / 1024 threads = 4 per thread, vectorized
    const int t0 = tid * 4;
    const float4 sc = ((const float4*)(g_score + b * NT))[tid];
    float4 a;
    a.x = (t0 + 0 < len) ? __expf(sc.x - M) * invD : 0.f;
    a.y = (t0 + 1 < len) ? __expf(sc.y - M) * invD : 0.f;
    a.z = (t0 + 2 < len) ? __expf(sc.z - M) * invD : 0.f;
    a.w = (t0 + 3 < len) ? __expf(sc.w - M) * invD : 0.f;
    ((float4*)(out_a + b * NT))[tid] = a;
}

// ---------------------------------------------------------------------------
extern "C" void kernel_launch(void* const* d_in, const int* in_sizes, int n_in,
                              void* d_out, int out_size) {
    // Resolve inputs by element count (all five are distinct):
    // encoder_h 67108864 | decoder_s 16384 | mask 262144 | Wa_w 65536 | Wa_b 256
    const float* h    = nullptr;
    const float* dec  = nullptr;
    const int*   mask = nullptr;
    const float* W    = nullptr;
    const float* bias = nullptr;
    for (int i = 0; i < n_in; ++i) {
        switch (in_sizes[i]) {
            case NB * NT * NU:  h    = (const float*)d_in[i]; break;
            case NB * NDEC:     dec  = (const float*)d_in[i]; break;
            case NB * NT:       mask = (const int*)  d_in[i]; break;
            case NDEC * NU:     W    = (const float*)d_in[i]; break;
            case NU:            bias = (const float*)d_in[i]; break;
        }
    }
    float* out = (float*)d_out;

    k_state <<<NB * 8, 256>>>(dec, W, bias);
    k_scores<<<NB * NSPLIT, 256>>>(h, mask);
    k_final <<<NB, 1024>>>(out, out + NB * NU);
}